// round 6
// baseline (speedup 1.0000x reference)
#include <cuda_runtime.h>

// Quaternion tensor product (Hamilton product per lane e):
//   o0 = a0*b0 - a1*b1 - a2*b2 - a3*b3
//   o1 = a0*b1 + a1*b0 + a2*b3 - a3*b2
//   o2 = a0*b2 - a1*b3 + a2*b0 + a3*b1
//   o3 = a0*b3 + a1*b2 - a2*b1 + a3*b0
// Pure streaming, zero reuse. 1.07 GB read + 0.54 GB write.
// 256-bit LDG/STG (32B aligned aggregates) + persistent grid-stride loop so
// next-iteration loads overlap current-iteration stores (continuous MLP,
// no wave-transition bubbles).

#define EXTENT 128
#define NSEG 4
#define CHUNKS_PER_ROW (EXTENT / 8)  // 16 threads-worth of work per row

struct __align__(32) F8 { float4 lo, hi; };

__device__ __forceinline__ float4 quat0(const float4&a0,const float4&a1,const float4&a2,const float4&a3,
                                        const float4&b0,const float4&b1,const float4&b2,const float4&b3){
    float4 o;
    o.x = a0.x*b0.x - a1.x*b1.x - a2.x*b2.x - a3.x*b3.x;
    o.y = a0.y*b0.y - a1.y*b1.y - a2.y*b2.y - a3.y*b3.y;
    o.z = a0.z*b0.z - a1.z*b1.z - a2.z*b2.z - a3.z*b3.z;
    o.w = a0.w*b0.w - a1.w*b1.w - a2.w*b2.w - a3.w*b3.w;
    return o;
}
__device__ __forceinline__ float4 quat1(const float4&a0,const float4&a1,const float4&a2,const float4&a3,
                                        const float4&b0,const float4&b1,const float4&b2,const float4&b3){
    float4 o;
    o.x = a0.x*b1.x + a1.x*b0.x + a2.x*b3.x - a3.x*b2.x;
    o.y = a0.y*b1.y + a1.y*b0.y + a2.y*b3.y - a3.y*b2.y;
    o.z = a0.z*b1.z + a1.z*b0.z + a2.z*b3.z - a3.z*b2.z;
    o.w = a0.w*b1.w + a1.w*b0.w + a2.w*b3.w - a3.w*b2.w;
    return o;
}
__device__ __forceinline__ float4 quat2(const float4&a0,const float4&a1,const float4&a2,const float4&a3,
                                        const float4&b0,const float4&b1,const float4&b2,const float4&b3){
    float4 o;
    o.x = a0.x*b2.x - a1.x*b3.x + a2.x*b0.x + a3.x*b1.x;
    o.y = a0.y*b2.y - a1.y*b3.y + a2.y*b0.y + a3.y*b1.y;
    o.z = a0.z*b2.z - a1.z*b3.z + a2.z*b0.z + a3.z*b1.z;
    o.w = a0.w*b2.w - a1.w*b3.w + a2.w*b0.w + a3.w*b1.w;
    return o;
}
__device__ __forceinline__ float4 quat3(const float4&a0,const float4&a1,const float4&a2,const float4&a3,
                                        const float4&b0,const float4&b1,const float4&b2,const float4&b3){
    float4 o;
    o.x = a0.x*b3.x + a1.x*b2.x - a2.x*b1.x + a3.x*b0.x;
    o.y = a0.y*b3.y + a1.y*b2.y - a2.y*b1.y + a3.y*b0.y;
    o.z = a0.z*b3.z + a1.z*b2.z - a2.z*b1.z + a3.z*b0.z;
    o.w = a0.w*b3.w + a1.w*b2.w - a2.w*b1.w + a3.w*b0.w;
    return o;
}

__global__ void __launch_bounds__(256) quat_tp_kernel(
    const F8* __restrict__ in0,
    const F8* __restrict__ in1,
    F8* __restrict__ out,
    long long total_chunks)          // BATCH * CHUNKS_PER_ROW
{
    long long stride = (long long)gridDim.x * blockDim.x;
    long long g0 = (long long)blockIdx.x * blockDim.x + threadIdx.x;

    #pragma unroll 1
    for (long long g = g0; g < total_chunks; g += stride) {
        long long b = g >> 4;            // row index
        int       t = (int)(g & 15);     // 32B chunk within a segment

        // F8 units: row = 64 F8, segment = 16 F8
        const F8* p0 = in0 + b * 64 + t;
        const F8* p1 = in1 + b * 64 + t;
        F8*       po = out + b * 64 + t;

        // 8 independent 256-bit loads (512 B in flight per thread)
        F8 a0 = p0[0 * 16];
        F8 a1 = p0[1 * 16];
        F8 a2 = p0[2 * 16];
        F8 a3 = p0[3 * 16];
        F8 b0 = p1[0 * 16];
        F8 b1 = p1[1 * 16];
        F8 b2 = p1[2 * 16];
        F8 b3 = p1[3 * 16];

        F8 o0, o1, o2, o3;
        o0.lo = quat0(a0.lo,a1.lo,a2.lo,a3.lo, b0.lo,b1.lo,b2.lo,b3.lo);
        o0.hi = quat0(a0.hi,a1.hi,a2.hi,a3.hi, b0.hi,b1.hi,b2.hi,b3.hi);
        o1.lo = quat1(a0.lo,a1.lo,a2.lo,a3.lo, b0.lo,b1.lo,b2.lo,b3.lo);
        o1.hi = quat1(a0.hi,a1.hi,a2.hi,a3.hi, b0.hi,b1.hi,b2.hi,b3.hi);
        o2.lo = quat2(a0.lo,a1.lo,a2.lo,a3.lo, b0.lo,b1.lo,b2.lo,b3.lo);
        o2.hi = quat2(a0.hi,a1.hi,a2.hi,a3.hi, b0.hi,b1.hi,b2.hi,b3.hi);
        o3.lo = quat3(a0.lo,a1.lo,a2.lo,a3.lo, b0.lo,b1.lo,b2.lo,b3.lo);
        o3.hi = quat3(a0.hi,a1.hi,a2.hi,a3.hi, b0.hi,b1.hi,b2.hi,b3.hi);

        po[0 * 16] = o0;
        po[1 * 16] = o1;
        po[2 * 16] = o2;
        po[3 * 16] = o3;
    }
}

extern "C" void kernel_launch(void* const* d_in, const int* in_sizes, int n_in,
                              void* d_out, int out_size) {
    const F8* in0 = (const F8*)d_in[0];
    const F8* in1 = (const F8*)d_in[1];
    F8* out = (F8*)d_out;

    long long batch = (long long)in_sizes[0] / (NSEG * EXTENT);   // 262144
    long long total_chunks = batch * CHUNKS_PER_ROW;              // 4194304

    // Persistent: 3 CTAs/SM (80 regs, 256 thr) x 148 SMs = 444 resident CTAs
    int threads = 256;
    int blocks = 148 * 3;
    quat_tp_kernel<<<blocks, threads>>>(in0, in1, out, total_chunks);
}

// round 9
// speedup vs baseline: 1.0559x; 1.0559x over previous
#include <cuda_runtime.h>

// Quaternion tensor product (Hamilton product per lane e):
//   o0 = a0*b0 - a1*b1 - a2*b2 - a3*b3
//   o1 = a0*b1 + a1*b0 + a2*b3 - a3*b2
//   o2 = a0*b2 - a1*b3 + a2*b0 + a3*b1
//   o3 = a0*b3 + a1*b2 - a2*b1 + a3*b0
// Pure streaming, zero reuse. 1.07 GB read + 0.54 GB write.
// Flat exact launch (NOT persistent — R6 showed the loop costs MLP),
// 256-bit LDG/STG via 32B-aligned aggregates, store each output as soon
// as it is computed to shorten live ranges and start the write stream early.

#define EXTENT 128
#define NSEG 4
#define CHUNKS_PER_ROW (EXTENT / 8)  // 16 threads per row (8 lanes each)

struct __align__(32) F8 { float4 lo, hi; };

__device__ __forceinline__ float4 quat0(const float4&a0,const float4&a1,const float4&a2,const float4&a3,
                                        const float4&b0,const float4&b1,const float4&b2,const float4&b3){
    float4 o;
    o.x = a0.x*b0.x - a1.x*b1.x - a2.x*b2.x - a3.x*b3.x;
    o.y = a0.y*b0.y - a1.y*b1.y - a2.y*b2.y - a3.y*b3.y;
    o.z = a0.z*b0.z - a1.z*b1.z - a2.z*b2.z - a3.z*b3.z;
    o.w = a0.w*b0.w - a1.w*b1.w - a2.w*b2.w - a3.w*b3.w;
    return o;
}
__device__ __forceinline__ float4 quat1(const float4&a0,const float4&a1,const float4&a2,const float4&a3,
                                        const float4&b0,const float4&b1,const float4&b2,const float4&b3){
    float4 o;
    o.x = a0.x*b1.x + a1.x*b0.x + a2.x*b3.x - a3.x*b2.x;
    o.y = a0.y*b1.y + a1.y*b0.y + a2.y*b3.y - a3.y*b2.y;
    o.z = a0.z*b1.z + a1.z*b0.z + a2.z*b3.z - a3.z*b2.z;
    o.w = a0.w*b1.w + a1.w*b0.w + a2.w*b3.w - a3.w*b2.w;
    return o;
}
__device__ __forceinline__ float4 quat2(const float4&a0,const float4&a1,const float4&a2,const float4&a3,
                                        const float4&b0,const float4&b1,const float4&b2,const float4&b3){
    float4 o;
    o.x = a0.x*b2.x - a1.x*b3.x + a2.x*b0.x + a3.x*b1.x;
    o.y = a0.y*b2.y - a1.y*b3.y + a2.y*b0.y + a3.y*b1.y;
    o.z = a0.z*b2.z - a1.z*b3.z + a2.z*b0.z + a3.z*b1.z;
    o.w = a0.w*b2.w - a1.w*b3.w + a2.w*b0.w + a3.w*b1.w;
    return o;
}
__device__ __forceinline__ float4 quat3(const float4&a0,const float4&a1,const float4&a2,const float4&a3,
                                        const float4&b0,const float4&b1,const float4&b2,const float4&b3){
    float4 o;
    o.x = a0.x*b3.x + a1.x*b2.x - a2.x*b1.x + a3.x*b0.x;
    o.y = a0.y*b3.y + a1.y*b2.y - a2.y*b1.y + a3.y*b0.y;
    o.z = a0.z*b3.z + a1.z*b2.z - a2.z*b1.z + a3.z*b0.z;
    o.w = a0.w*b3.w + a1.w*b2.w - a2.w*b1.w + a3.w*b0.w;
    return o;
}

__global__ void __launch_bounds__(256) quat_tp_kernel(
    const F8* __restrict__ in0,
    const F8* __restrict__ in1,
    F8* __restrict__ out)
{
    // One thread = 8 consecutive lanes of one row. 16 threads per row.
    // Grid launched exactly; no bounds check.
    long long g = (long long)blockIdx.x * blockDim.x + threadIdx.x;
    long long b = g >> 4;            // row index
    int       t = (int)(g & 15);     // 32B chunk within a segment

    // F8 units: row = 64 F8, segment = 16 F8
    const F8* p0 = in0 + b * 64 + t;
    const F8* p1 = in1 + b * 64 + t;
    F8*       po = out + b * 64 + t;

    // 8 independent 256-bit loads, front-batched (512 B in flight per thread)
    F8 a0 = p0[0 * 16];
    F8 a1 = p0[1 * 16];
    F8 a2 = p0[2 * 16];
    F8 a3 = p0[3 * 16];
    F8 b0 = p1[0 * 16];
    F8 b1 = p1[1 * 16];
    F8 b2 = p1[2 * 16];
    F8 b3 = p1[3 * 16];

    // Compute + store each output immediately: shorter live ranges,
    // first STG issues before later FFMAs finish.
    F8 o;
    o.lo = quat0(a0.lo,a1.lo,a2.lo,a3.lo, b0.lo,b1.lo,b2.lo,b3.lo);
    o.hi = quat0(a0.hi,a1.hi,a2.hi,a3.hi, b0.hi,b1.hi,b2.hi,b3.hi);
    po[0 * 16] = o;

    o.lo = quat1(a0.lo,a1.lo,a2.lo,a3.lo, b0.lo,b1.lo,b2.lo,b3.lo);
    o.hi = quat1(a0.hi,a1.hi,a2.hi,a3.hi, b0.hi,b1.hi,b2.hi,b3.hi);
    po[1 * 16] = o;

    o.lo = quat2(a0.lo,a1.lo,a2.lo,a3.lo, b0.lo,b1.lo,b2.lo,b3.lo);
    o.hi = quat2(a0.hi,a1.hi,a2.hi,a3.hi, b0.hi,b1.hi,b2.hi,b3.hi);
    po[2 * 16] = o;

    o.lo = quat3(a0.lo,a1.lo,a2.lo,a3.lo, b0.lo,b1.lo,b2.lo,b3.lo);
    o.hi = quat3(a0.hi,a1.hi,a2.hi,a3.hi, b0.hi,b1.hi,b2.hi,b3.hi);
    po[3 * 16] = o;
}

extern "C" void kernel_launch(void* const* d_in, const int* in_sizes, int n_in,
                              void* d_out, int out_size) {
    const F8* in0 = (const F8*)d_in[0];
    const F8* in1 = (const F8*)d_in[1];
    F8* out = (F8*)d_out;

    long long batch = (long long)in_sizes[0] / (NSEG * EXTENT);   // 262144
    long long total_threads = batch * CHUNKS_PER_ROW;             // 4194304
    int threads = 256;
    long long blocks = (total_threads + threads - 1) / threads;   // exact: 16384
    quat_tp_kernel<<<(unsigned)blocks, threads>>>(in0, in1, out);
}

// round 11
// speedup vs baseline: 1.0617x; 1.0055x over previous
#include <cuda_runtime.h>

// Quaternion tensor product (Hamilton product per lane e):
//   o0 = a0*b0 - a1*b1 - a2*b2 - a3*b3
//   o1 = a0*b1 + a1*b0 + a2*b3 - a3*b2
//   o2 = a0*b2 - a1*b3 + a2*b0 + a3*b1
//   o3 = a0*b3 + a1*b2 - a2*b1 + a3*b0
// Pure streaming, zero reuse. 1.07 GB read + 0.54 GB write -> HBM-bound.
// Best-measured structure (R4): flat exact launch, 256-bit LDG/STG via
// 32B-aligned aggregates, 8 front-batched loads (512 B MLP/thread).
// This round: 512-thread blocks (only unexplored geometry).

#define EXTENT 128
#define NSEG 4
#define CHUNKS_PER_ROW (EXTENT / 8)  // 16 threads per row (8 lanes each)

struct __align__(32) F8 { float4 lo, hi; };

__device__ __forceinline__ float4 quat0(const float4&a0,const float4&a1,const float4&a2,const float4&a3,
                                        const float4&b0,const float4&b1,const float4&b2,const float4&b3){
    float4 o;
    o.x = a0.x*b0.x - a1.x*b1.x - a2.x*b2.x - a3.x*b3.x;
    o.y = a0.y*b0.y - a1.y*b1.y - a2.y*b2.y - a3.y*b3.y;
    o.z = a0.z*b0.z - a1.z*b1.z - a2.z*b2.z - a3.z*b3.z;
    o.w = a0.w*b0.w - a1.w*b1.w - a2.w*b2.w - a3.w*b3.w;
    return o;
}
__device__ __forceinline__ float4 quat1(const float4&a0,const float4&a1,const float4&a2,const float4&a3,
                                        const float4&b0,const float4&b1,const float4&b2,const float4&b3){
    float4 o;
    o.x = a0.x*b1.x + a1.x*b0.x + a2.x*b3.x - a3.x*b2.x;
    o.y = a0.y*b1.y + a1.y*b0.y + a2.y*b3.y - a3.y*b2.y;
    o.z = a0.z*b1.z + a1.z*b0.z + a2.z*b3.z - a3.z*b2.z;
    o.w = a0.w*b1.w + a1.w*b0.w + a2.w*b3.w - a3.w*b2.w;
    return o;
}
__device__ __forceinline__ float4 quat2(const float4&a0,const float4&a1,const float4&a2,const float4&a3,
                                        const float4&b0,const float4&b1,const float4&b2,const float4&b3){
    float4 o;
    o.x = a0.x*b2.x - a1.x*b3.x + a2.x*b0.x + a3.x*b1.x;
    o.y = a0.y*b2.y - a1.y*b3.y + a2.y*b0.y + a3.y*b1.y;
    o.z = a0.z*b2.z - a1.z*b3.z + a2.z*b0.z + a3.z*b1.z;
    o.w = a0.w*b2.w - a1.w*b3.w + a2.w*b0.w + a3.w*b1.w;
    return o;
}
__device__ __forceinline__ float4 quat3(const float4&a0,const float4&a1,const float4&a2,const float4&a3,
                                        const float4&b0,const float4&b1,const float4&b2,const float4&b3){
    float4 o;
    o.x = a0.x*b3.x + a1.x*b2.x - a2.x*b1.x + a3.x*b0.x;
    o.y = a0.y*b3.y + a1.y*b2.y - a2.y*b1.y + a3.y*b0.y;
    o.z = a0.z*b3.z + a1.z*b2.z - a2.z*b1.z + a3.z*b0.z;
    o.w = a0.w*b3.w + a1.w*b2.w - a2.w*b1.w + a3.w*b0.w;
    return o;
}

__global__ void __launch_bounds__(512) quat_tp_kernel(
    const F8* __restrict__ in0,
    const F8* __restrict__ in1,
    F8* __restrict__ out)
{
    // One thread = 8 consecutive lanes of one row. 16 threads per row.
    // Grid launched exactly; no bounds check.
    long long g = (long long)blockIdx.x * blockDim.x + threadIdx.x;
    long long b = g >> 4;            // row index
    int       t = (int)(g & 15);     // 32B chunk within a segment

    // F8 units: row = 64 F8, segment = 16 F8
    const F8* p0 = in0 + b * 64 + t;
    const F8* p1 = in1 + b * 64 + t;
    F8*       po = out + b * 64 + t;

    // 8 independent 256-bit loads, front-batched (512 B in flight per thread)
    F8 a0 = p0[0 * 16];
    F8 a1 = p0[1 * 16];
    F8 a2 = p0[2 * 16];
    F8 a3 = p0[3 * 16];
    F8 b0 = p1[0 * 16];
    F8 b1 = p1[1 * 16];
    F8 b2 = p1[2 * 16];
    F8 b3 = p1[3 * 16];

    F8 o0, o1, o2, o3;
    o0.lo = quat0(a0.lo,a1.lo,a2.lo,a3.lo, b0.lo,b1.lo,b2.lo,b3.lo);
    o0.hi = quat0(a0.hi,a1.hi,a2.hi,a3.hi, b0.hi,b1.hi,b2.hi,b3.hi);
    o1.lo = quat1(a0.lo,a1.lo,a2.lo,a3.lo, b0.lo,b1.lo,b2.lo,b3.lo);
    o1.hi = quat1(a0.hi,a1.hi,a2.hi,a3.hi, b0.hi,b1.hi,b2.hi,b3.hi);
    o2.lo = quat2(a0.lo,a1.lo,a2.lo,a3.lo, b0.lo,b1.lo,b2.lo,b3.lo);
    o2.hi = quat2(a0.hi,a1.hi,a2.hi,a3.hi, b0.hi,b1.hi,b2.hi,b3.hi);
    o3.lo = quat3(a0.lo,a1.lo,a2.lo,a3.lo, b0.lo,b1.lo,b2.lo,b3.lo);
    o3.hi = quat3(a0.hi,a1.hi,a2.hi,a3.hi, b0.hi,b1.hi,b2.hi,b3.hi);

    po[0 * 16] = o0;
    po[1 * 16] = o1;
    po[2 * 16] = o2;
    po[3 * 16] = o3;
}

extern "C" void kernel_launch(void* const* d_in, const int* in_sizes, int n_in,
                              void* d_out, int out_size) {
    const F8* in0 = (const F8*)d_in[0];
    const F8* in1 = (const F8*)d_in[1];
    F8* out = (F8*)d_out;

    long long batch = (long long)in_sizes[0] / (NSEG * EXTENT);   // 262144
    long long total_threads = batch * CHUNKS_PER_ROW;             // 4194304
    int threads = 512;
    long long blocks = (total_threads + threads - 1) / threads;   // exact: 8192
    quat_tp_kernel<<<(unsigned)blocks, threads>>>(in0, in1, out);
}

// round 14
// speedup vs baseline: 1.0680x; 1.0060x over previous
#include <cuda_runtime.h>

// Quaternion tensor product (Hamilton product per lane e):
//   o0 = a0*b0 - a1*b1 - a2*b2 - a3*b3
//   o1 = a0*b1 + a1*b0 + a2*b3 - a3*b2
//   o2 = a0*b2 - a1*b3 + a2*b0 + a3*b1
//   o3 = a0*b3 + a1*b2 - a2*b1 + a3*b0
// Pure streaming, zero reuse. 1.07 GB read + 0.54 GB write -> HBM-bound,
// measured at 7.15 TB/s (89% of spec) = the wall.
// Structure: flat exact launch, 512-thr blocks, 256-bit LDG/STG via
// 32B-aligned aggregates, 8 front-batched loads (512 B MLP/thread).
// This round: __ldcg loads (bypass L1 — zero reuse, skip useless fills).

#define EXTENT 128
#define NSEG 4
#define CHUNKS_PER_ROW (EXTENT / 8)  // 16 threads per row (8 lanes each)

struct __align__(32) F8 { float4 lo, hi; };

__device__ __forceinline__ F8 ldcg8(const F8* p) {
    F8 r;
    r.lo = __ldcg((const float4*)p);
    r.hi = __ldcg(((const float4*)p) + 1);
    return r;
}

__device__ __forceinline__ float4 quat0(const float4&a0,const float4&a1,const float4&a2,const float4&a3,
                                        const float4&b0,const float4&b1,const float4&b2,const float4&b3){
    float4 o;
    o.x = a0.x*b0.x - a1.x*b1.x - a2.x*b2.x - a3.x*b3.x;
    o.y = a0.y*b0.y - a1.y*b1.y - a2.y*b2.y - a3.y*b3.y;
    o.z = a0.z*b0.z - a1.z*b1.z - a2.z*b2.z - a3.z*b3.z;
    o.w = a0.w*b0.w - a1.w*b1.w - a2.w*b2.w - a3.w*b3.w;
    return o;
}
__device__ __forceinline__ float4 quat1(const float4&a0,const float4&a1,const float4&a2,const float4&a3,
                                        const float4&b0,const float4&b1,const float4&b2,const float4&b3){
    float4 o;
    o.x = a0.x*b1.x + a1.x*b0.x + a2.x*b3.x - a3.x*b2.x;
    o.y = a0.y*b1.y + a1.y*b0.y + a2.y*b3.y - a3.y*b2.y;
    o.z = a0.z*b1.z + a1.z*b0.z + a2.z*b3.z - a3.z*b2.z;
    o.w = a0.w*b1.w + a1.w*b0.w + a2.w*b3.w - a3.w*b2.w;
    return o;
}
__device__ __forceinline__ float4 quat2(const float4&a0,const float4&a1,const float4&a2,const float4&a3,
                                        const float4&b0,const float4&b1,const float4&b2,const float4&b3){
    float4 o;
    o.x = a0.x*b2.x - a1.x*b3.x + a2.x*b0.x + a3.x*b1.x;
    o.y = a0.y*b2.y - a1.y*b3.y + a2.y*b0.y + a3.y*b1.y;
    o.z = a0.z*b2.z - a1.z*b3.z + a2.z*b0.z + a3.z*b1.z;
    o.w = a0.w*b2.w - a1.w*b3.w + a2.w*b0.w + a3.w*b1.w;
    return o;
}
__device__ __forceinline__ float4 quat3(const float4&a0,const float4&a1,const float4&a2,const float4&a3,
                                        const float4&b0,const float4&b1,const float4&b2,const float4&b3){
    float4 o;
    o.x = a0.x*b3.x + a1.x*b2.x - a2.x*b1.x + a3.x*b0.x;
    o.y = a0.y*b3.y + a1.y*b2.y - a2.y*b1.y + a3.y*b0.y;
    o.z = a0.z*b3.z + a1.z*b2.z - a2.z*b1.z + a3.z*b0.z;
    o.w = a0.w*b3.w + a1.w*b2.w - a2.w*b1.w + a3.w*b0.w;
    return o;
}

__global__ void __launch_bounds__(512) quat_tp_kernel(
    const F8* __restrict__ in0,
    const F8* __restrict__ in1,
    F8* __restrict__ out)
{
    // One thread = 8 consecutive lanes of one row. 16 threads per row.
    // Grid launched exactly; no bounds check.
    long long g = (long long)blockIdx.x * blockDim.x + threadIdx.x;
    long long b = g >> 4;            // row index
    int       t = (int)(g & 15);     // 32B chunk within a segment

    // F8 units: row = 64 F8, segment = 16 F8
    const F8* p0 = in0 + b * 64 + t;
    const F8* p1 = in1 + b * 64 + t;
    F8*       po = out + b * 64 + t;

    // 8 independent 256-bit L2-only loads, front-batched
    F8 a0 = ldcg8(p0 + 0 * 16);
    F8 a1 = ldcg8(p0 + 1 * 16);
    F8 a2 = ldcg8(p0 + 2 * 16);
    F8 a3 = ldcg8(p0 + 3 * 16);
    F8 b0 = ldcg8(p1 + 0 * 16);
    F8 b1 = ldcg8(p1 + 1 * 16);
    F8 b2 = ldcg8(p1 + 2 * 16);
    F8 b3 = ldcg8(p1 + 3 * 16);

    F8 o0, o1, o2, o3;
    o0.lo = quat0(a0.lo,a1.lo,a2.lo,a3.lo, b0.lo,b1.lo,b2.lo,b3.lo);
    o0.hi = quat0(a0.hi,a1.hi,a2.hi,a3.hi, b0.hi,b1.hi,b2.hi,b3.hi);
    o1.lo = quat1(a0.lo,a1.lo,a2.lo,a3.lo, b0.lo,b1.lo,b2.lo,b3.lo);
    o1.hi = quat1(a0.hi,a1.hi,a2.hi,a3.hi, b0.hi,b1.hi,b2.hi,b3.hi);
    o2.lo = quat2(a0.lo,a1.lo,a2.lo,a3.lo, b0.lo,b1.lo,b2.lo,b3.lo);
    o2.hi = quat2(a0.hi,a1.hi,a2.hi,a3.hi, b0.hi,b1.hi,b2.hi,b3.hi);
    o3.lo = quat3(a0.lo,a1.lo,a2.lo,a3.lo, b0.lo,b1.lo,b2.lo,b3.lo);
    o3.hi = quat3(a0.hi,a1.hi,a2.hi,a3.hi, b0.hi,b1.hi,b2.hi,b3.hi);

    po[0 * 16] = o0;
    po[1 * 16] = o1;
    po[2 * 16] = o2;
    po[3 * 16] = o3;
}

extern "C" void kernel_launch(void* const* d_in, const int* in_sizes, int n_in,
                              void* d_out, int out_size) {
    const F8* in0 = (const F8*)d_in[0];
    const F8* in1 = (const F8*)d_in[1];
    F8* out = (F8*)d_out;

    long long batch = (long long)in_sizes[0] / (NSEG * EXTENT);   // 262144
    long long total_threads = batch * CHUNKS_PER_ROW;             // 4194304
    int threads = 512;
    long long blocks = (total_threads + threads - 1) / threads;   // exact: 8192
    quat_tp_kernel<<<(unsigned)blocks, threads>>>(in0, in1, out);
}